// round 13
// baseline (speedup 1.0000x reference)
#include <cuda_runtime.h>
#include <cuda_fp16.h>
#include <math.h>
#include <stdint.h>

#define TT 2048
#define DIM 2048
#define NEXP 32
#define TOPK 4
#define INTER 1024
#define SHIN 2048
#define NA (TT*TOPK)
#define BM 128
#define MAXTILES (NA/BM + NEXP)   /* 96 */

#define KC 64                     /* K halfs per chunk */
#define RW 36                     /* words per fp16 stage row (32 data + 4 pad) */
#define STGW (384*RW)             /* 13824 words per stage (A 128 + B 256 rows) */

#define UP_RB   (MAXTILES * 8)    /* routed up: 96 x (1024/128) */
#define UP_SB   (16 * 16)         /* shared up: 16 x (2048/128) */
#define DN_RB   (MAXTILES * 8)    /* routed down: 96 x (2048/256) */
#define DN_SB   (16 * 8)          /* shared down: 16 x (2048/256) */

// ---------------- device scratch ----------------
__device__ int   g_topi[TT*TOPK];
__device__ float g_topw[TT*TOPK];
__device__ int   g_cnt[NEXP];
__device__ int   g_off[NEXP+1];
__device__ int   g_tok[NA];
__device__ float g_wt[NA];
__device__ int   g_tile_e[MAXTILES];
__device__ int   g_tile_r0[MAXTILES];
__device__ int   g_tile_n[MAXTILES];
__device__ int   g_ntiles;

// fp16 copies (converted once per call)
__device__ __half h_w1[(size_t)NEXP*INTER*DIM];
__device__ __half h_w2[(size_t)NEXP*DIM*INTER];
__device__ __half h_w3[(size_t)NEXP*INTER*DIM];
__device__ __half h_sw1[(size_t)SHIN*DIM];
__device__ __half h_sw2[(size_t)DIM*SHIN];
__device__ __half h_sw3[(size_t)SHIN*DIM];
__device__ __half h_x[(size_t)TT*DIM];
__device__ __half h_h[(size_t)NA*INTER];
__device__ __half h_hs[(size_t)TT*SHIN];

// ---------------- helpers ----------------
__device__ __forceinline__ uint32_t smem_u32(const void* p) {
    uint32_t a;
    asm("{ .reg .u64 t; cvta.to.shared.u64 t, %1; cvt.u32.u64 %0, t; }" : "=r"(a) : "l"(p));
    return a;
}
__device__ __forceinline__ uint32_t pk16(float lo, float hi) {
    uint32_t r; asm("cvt.rn.f16x2.f32 %0, %1, %2;" : "=r"(r) : "f"(hi), "f"(lo)); return r;
}
__device__ __forceinline__ void cp16(uint32_t dst, const void* src) {
    asm volatile("cp.async.cg.shared.global [%0], [%1], 16;" :: "r"(dst), "l"(src));
}
#define CP_COMMIT() asm volatile("cp.async.commit_group;" ::: "memory")
template<int N>
__device__ __forceinline__ void cp_wait() {
    asm volatile("cp.async.wait_group %0;" :: "n"(N) : "memory");
}
__device__ __forceinline__ void mma16(float* c, const uint32_t* a, uint32_t b0, uint32_t b1) {
    asm volatile("mma.sync.aligned.m16n8k16.row.col.f32.f16.f16.f32 "
        "{%0,%1,%2,%3}, {%4,%5,%6,%7}, {%8,%9}, {%0,%1,%2,%3};"
        : "+f"(c[0]), "+f"(c[1]), "+f"(c[2]), "+f"(c[3])
        : "r"(a[0]), "r"(a[1]), "r"(a[2]), "r"(a[3]), "r"(b0), "r"(b1));
}
__device__ __forceinline__ void ldsm4(uint32_t* r, uint32_t addr) {
    asm volatile("ldmatrix.sync.aligned.m8n8.x4.shared.b16 {%0,%1,%2,%3}, [%4];"
        : "=r"(r[0]), "=r"(r[1]), "=r"(r[2]), "=r"(r[3]) : "r"(addr));
}
__device__ __forceinline__ float silu_f(float v) { return v / (1.0f + __expf(-v)); }

// ---------------- fp32 -> fp16 convert, ILP=4, streaming ----------------
__global__ __launch_bounds__(256) void k_f2h(const float4* __restrict__ src,
                                             uint2* __restrict__ dst, int n4) {
    int base = blockIdx.x * 1024 + threadIdx.x;
    int i0 = base, i1 = base + 256, i2 = base + 512, i3 = base + 768;
    if (i3 < n4) {
        float4 v0 = __ldcs(src + i0);
        float4 v1 = __ldcs(src + i1);
        float4 v2 = __ldcs(src + i2);
        float4 v3 = __ldcs(src + i3);
        uint2 w0, w1, w2, w3;
        w0.x = pk16(v0.x, v0.y); w0.y = pk16(v0.z, v0.w);
        w1.x = pk16(v1.x, v1.y); w1.y = pk16(v1.z, v1.w);
        w2.x = pk16(v2.x, v2.y); w2.y = pk16(v2.z, v2.w);
        w3.x = pk16(v3.x, v3.y); w3.y = pk16(v3.z, v3.w);
        __stcs(dst + i0, w0);
        __stcs(dst + i1, w1);
        __stcs(dst + i2, w2);
        __stcs(dst + i3, w3);
    } else {
        for (int i = i0; i < n4; i += 256) {
            float4 v = __ldcs(src + i);
            uint2 w;
            w.x = pk16(v.x, v.y); w.y = pk16(v.z, v.w);
            __stcs(dst + i, w);
        }
    }
}

// ---------------- kernel 0: zero counters ----------------
__global__ void k_zero() {
    if (threadIdx.x < NEXP) g_cnt[threadIdx.x] = 0;
}

// ---------------- kernel 0b: zero output ----------------
__global__ __launch_bounds__(256) void k_zero_out(float* __restrict__ out) {
    int i = (blockIdx.x * 256 + threadIdx.x) * 4;
    float4 z = make_float4(0.f, 0.f, 0.f, 0.f);
    *(float4*)(out + i) = z;
}

// ---------------- kernel 1: gate (fp32 exact) ----------------
__global__ __launch_bounds__(128) void k_gate(const float* __restrict__ x,
                                              const float* __restrict__ gw) {
    __shared__ float sx[DIM];
    __shared__ float slog[NEXP];
    int t = blockIdx.x;
    const float* xr = x + (size_t)t * DIM;
    for (int i = threadIdx.x * 4; i < DIM; i += 128 * 4)
        *(float4*)(sx + i) = *(const float4*)(xr + i);
    __syncthreads();

    int e = threadIdx.x >> 2, part = threadIdx.x & 3;
    const float* wr = gw + (size_t)e * DIM;
    float s = 0.f;
    for (int k = part * 4; k < DIM; k += 16) {
        float4 a = *(const float4*)(sx + k);
        float4 b = *(const float4*)(wr + k);
        s += a.x * b.x + a.y * b.y + a.z * b.z + a.w * b.w;
    }
    s += __shfl_down_sync(0xffffffffu, s, 2, 4);
    s += __shfl_down_sync(0xffffffffu, s, 1, 4);
    if (part == 0) slog[e] = s;
    __syncthreads();

    if (threadIdx.x < 32) {
        float sc = slog[threadIdx.x];
        float m = sc;
        for (int o = 16; o; o >>= 1) m = fmaxf(m, __shfl_xor_sync(0xffffffffu, m, o));
        float p = expf(sc - m);
        float sum = p;
        for (int o = 16; o; o >>= 1) sum += __shfl_xor_sync(0xffffffffu, sum, o);
        float v = p / sum;
        for (int r = 0; r < TOPK; r++) {
            float mv = v;
            for (int o = 16; o; o >>= 1) mv = fmaxf(mv, __shfl_xor_sync(0xffffffffu, mv, o));
            unsigned bal = __ballot_sync(0xffffffffu, v == mv);
            int idx = __ffs(bal) - 1;
            if (threadIdx.x == 0) {
                g_topi[t * TOPK + r] = idx;
                g_topw[t * TOPK + r] = mv;
                atomicAdd(&g_cnt[idx], 1);
            }
            if (threadIdx.x == idx) v = -1.f;
        }
    }
}

// ---------------- kernel 2: offsets + tile map (1 warp, parallel) ---------
__global__ __launch_bounds__(32) void k_build() {
    int lane = threadIdx.x;
    int n = g_cnt[lane];
    int off = n;
    #pragma unroll
    for (int o = 1; o < 32; o <<= 1) {
        int v = __shfl_up_sync(0xffffffffu, off, o);
        if (lane >= o) off += v;
    }
    int excl = off - n;
    g_off[lane] = excl;
    if (lane == 31) g_off[NEXP] = off;

    int nt = (n + BM - 1) / BM;
    int tb = nt;
    #pragma unroll
    for (int o = 1; o < 32; o <<= 1) {
        int v = __shfl_up_sync(0xffffffffu, tb, o);
        if (lane >= o) tb += v;
    }
    int texcl = tb - nt;
    if (lane == 31) g_ntiles = tb;
    for (int t = 0; t < nt; t++) {
        g_tile_e[texcl + t]  = lane;
        g_tile_r0[texcl + t] = excl + t * BM;
        g_tile_n[texcl + t]  = min(BM, n - t * BM);
    }
}

// ---------------- kernel 3: parallel deterministic scatter ----------------
__global__ __launch_bounds__(256) void k_scatter() {
    int e = blockIdx.x, tid = threadIdx.x, w = tid >> 5, lane = tid & 31;
    __shared__ int wc[8];
    int t0 = w * 256;
    int cnt = 0;
    for (int i = 0; i < 8; i++) {
        int t = t0 + i * 32 + lane;
        bool f = false;
        #pragma unroll
        for (int k = 0; k < TOPK; k++) if (g_topi[t * TOPK + k] == e) f = true;
        cnt += __popc(__ballot_sync(0xffffffffu, f));
    }
    if (lane == 0) wc[w] = cnt;
    __syncthreads();
    int base = g_off[e];
    for (int ww = 0; ww < w; ww++) base += wc[ww];
    for (int i = 0; i < 8; i++) {
        int t = t0 + i * 32 + lane;
        float wt = 0.f; bool f = false;
        #pragma unroll
        for (int k = 0; k < TOPK; k++)
            if (g_topi[t * TOPK + k] == e) { f = true; wt = g_topw[t * TOPK + k]; }
        unsigned bal = __ballot_sync(0xffffffffu, f);
        int pos = base + __popc(bal & ((1u << lane) - 1u));
        if (f) { g_tok[pos] = t; g_wt[pos] = wt; }
        base += __popc(bal);
    }
}

// ---------------- merged up kernel: 128x128, 512 thr, 3-stage -------------
__global__ __launch_bounds__(512, 1) void k_up() {
    constexpr int NCH = DIM / KC;             // 32

    extern __shared__ uint32_t sm[];
    __shared__ int s_tok[BM];

    int bid = blockIdx.x;
    int e = 0, r0, nvalid = BM, jblk;
    const __half *pw1, *pw3;
    __half* dstH; int dstride, ni;
    bool routed = bid < UP_RB;
    if (routed) {
        int tile = bid >> 3;
        if (tile >= g_ntiles) return;
        jblk = (bid & 7) * 128;
        e = g_tile_e[tile]; r0 = g_tile_r0[tile]; nvalid = g_tile_n[tile];
        pw1 = h_w1; pw3 = h_w3; dstH = h_h; dstride = INTER; ni = INTER;
    } else {
        int sid = bid - UP_RB;
        int tile = sid >> 4;
        jblk = (sid & 15) * 128;
        r0 = tile * BM;
        pw1 = h_sw1; pw3 = h_sw3; dstH = h_hs; dstride = SHIN; ni = SHIN;
    }

    int tid = threadIdx.x, wid = tid >> 5, lane = tid & 31;
    int wm = wid & 3, wn = wid >> 2;          // 4 x 4 warps
    int gq = lane >> 2, cq = lane & 3;

    if (tid < BM)
        s_tok[tid] = routed ? g_tok[r0 + min(tid, nvalid - 1)] : (r0 + tid);
    __syncthreads();

    // loader: 6 x 16B (8 halfs) segments per thread per chunk (3072 slots)
    const __half* gp[6];
    uint32_t so[6];
    uint32_t smu = smem_u32(sm);
    #pragma unroll
    for (int j = 0; j < 6; j++) {
        int id = tid + j * 512;
        int s = id & 7;
        if (id < 1024) {
            int r = id >> 3;
            so[j] = (uint32_t)(r * RW + s * 4);
            gp[j] = h_x + (size_t)s_tok[r] * DIM + s * 8;
        } else {
            int rb = (id - 1024) >> 3;
            so[j] = (uint32_t)((128 + rb) * RW + s * 4);
            if (rb < 128) gp[j] = pw1 + ((size_t)e * ni + jblk + rb) * DIM + s * 8;
            else          gp[j] = pw3 + ((size_t)e * ni + jblk + (rb - 128)) * DIM + s * 8;
        }
    }

    float acc1[2][4][4], acc3[2][4][4];
    #pragma unroll
    for (int i = 0; i < 2; i++)
        #pragma unroll
        for (int j = 0; j < 4; j++)
            #pragma unroll
            for (int q = 0; q < 4; q++) { acc1[i][j][q] = 0.f; acc3[i][j][q] = 0.f; }

    uint32_t laneOff = (uint32_t)((lane & 15) * (RW * 4) + ((lane & 16) ? 16 : 0));

    #pragma unroll
    for (int j = 0; j < 6; j++) cp16(smu + so[j] * 4, gp[j]);
    CP_COMMIT();
    #pragma unroll
    for (int j = 0; j < 6; j++) cp16(smu + (STGW + so[j]) * 4, gp[j] + KC);
    CP_COMMIT();

    for (int c = 0; c < NCH; c++) {
        int st = c % 3;
        cp_wait<1>();
        __syncthreads();

        uint32_t hA = smu + (uint32_t)(st * STGW) * 4;
        uint32_t hB = hA + 128 * RW * 4;

        #pragma unroll
        for (int ks = 0; ks < 4; ks++) {
            uint32_t ko = (uint32_t)(ks * 32);
            uint32_t a[2][4];
            #pragma unroll
            for (int i = 0; i < 2; i++)
                ldsm4(a[i], hA + (uint32_t)((wm * 32 + i * 16) * (RW * 4)) + ko + laneOff);
            uint32_t b1[2][4], b3[2][4];
            #pragma unroll
            for (int j2 = 0; j2 < 2; j2++) {
                int nb = wn * 32 + j2 * 16;
                ldsm4(b1[j2], hB + (uint32_t)(nb * (RW * 4)) + ko + laneOff);
                ldsm4(b3[j2], hB + (uint32_t)((128 + nb) * (RW * 4)) + ko + laneOff);
            }
            #pragma unroll
            for (int i = 0; i < 2; i++)
                #pragma unroll
                for (int j2 = 0; j2 < 2; j2++) {
                    mma16(acc1[i][j2 * 2 + 0], a[i], b1[j2][0], b1[j2][2]);
                    mma16(acc1[i][j2 * 2 + 1], a[i], b1[j2][1], b1[j2][3]);
                    mma16(acc3[i][j2 * 2 + 0], a[i], b3[j2][0], b3[j2][2]);
                    mma16(acc3[i][j2 * 2 + 1], a[i], b3[j2][1], b3[j2][3]);
                }
        }

        if (c + 2 < NCH) {
            int st2 = (c + 2) % 3;
            int kb = (c + 2) * KC;
            #pragma unroll
            for (int j = 0; j < 6; j++)
                cp16(smu + (st2 * STGW + so[j]) * 4, gp[j] + kb);
        }
        CP_COMMIT();
    }

    #pragma unroll
    for (int i = 0; i < 2; i++) {
        int rbase = wm * 32 + i * 16 + gq;
        #pragma unroll
        for (int j = 0; j < 4; j++) {
            int col = jblk + wn * 32 + j * 8 + 2 * cq;
            if (rbase < nvalid) {
                uint32_t o = pk16(silu_f(acc1[i][j][0]) * acc3[i][j][0],
                                  silu_f(acc1[i][j][1]) * acc3[i][j][1]);
                *(uint32_t*)(dstH + (size_t)(r0 + rbase) * dstride + col) = o;
            }
            if (rbase + 8 < nvalid) {
                uint32_t o = pk16(silu_f(acc1[i][j][2]) * acc3[i][j][2],
                                  silu_f(acc1[i][j][3]) * acc3[i][j][3]);
                *(uint32_t*)(dstH + (size_t)(r0 + rbase + 8) * dstride + col) = o;
            }
        }
    }
}

// ---------------- merged down kernel: 128x256, 512 thr, 3-stage -----------
__global__ __launch_bounds__(512, 1) void k_down(float* __restrict__ out) {
    extern __shared__ uint32_t sm[];
    __shared__ int   s_tok[BM];
    __shared__ float s_wtv[BM];

    int bid = blockIdx.x;
    int e = 0, r0, nvalid = BM, dblk, kd, nch;
    const __half* srcH; int sstride;
    const __half* pb;
    bool routed = bid < DN_RB;
    if (routed) {
        int tile = bid >> 3;
        if (tile >= g_ntiles) return;
        dblk = (bid & 7) * 256;
        e = g_tile_e[tile]; r0 = g_tile_r0[tile]; nvalid = g_tile_n[tile];
        srcH = h_h; sstride = INTER; kd = INTER; nch = INTER / KC;     // 16
        pb = h_w2;
    } else {
        int sid = bid - DN_RB;
        int tile = sid >> 3;
        dblk = (sid & 7) * 256;
        r0 = tile * BM;
        srcH = h_hs; sstride = SHIN; kd = SHIN; nch = SHIN / KC;       // 32
        pb = h_sw2;
    }

    int tid = threadIdx.x, wid = tid >> 5, lane = tid & 31;
    int wm = wid & 3, wn = wid >> 2;          // 4 x 4 warps
    int gq = lane >> 2, cq = lane & 3;

    if (tid < BM) {
        if (routed) {
            int ok = tid < nvalid;
            s_tok[tid] = ok ? g_tok[r0 + tid] : 0;
            s_wtv[tid] = ok ? g_wt[r0 + tid]  : 0.f;
        } else { s_tok[tid] = r0 + tid; s_wtv[tid] = 1.f; }
    }
    __syncthreads();

    const __half* gp[6];
    uint32_t so[6];
    uint32_t smu = smem_u32(sm);
    #pragma unroll
    for (int j = 0; j < 6; j++) {
        int id = tid + j * 512;
        int s = id & 7;
        if (id < 1024) {
            int r = id >> 3;
            so[j] = (uint32_t)(r * RW + s * 4);
            gp[j] = srcH + (size_t)min(r0 + r, (routed ? NA : TT) - 1) * sstride + s * 8;
        } else {
            int rb = (id - 1024) >> 3;
            so[j] = (uint32_t)((128 + rb) * RW + s * 4);
            gp[j] = pb + ((size_t)e * DIM + dblk + rb) * kd + s * 8;
        }
    }

    float acc[2][8][4];
    #pragma unroll
    for (int i = 0; i < 2; i++)
        #pragma unroll
        for (int j = 0; j < 8; j++)
            #pragma unroll
            for (int q = 0; q < 4; q++) acc[i][j][q] = 0.f;

    uint32_t laneOff = (uint32_t)((lane & 15) * (RW * 4) + ((lane & 16) ? 16 : 0));

    #pragma unroll
    for (int j = 0; j < 6; j++) cp16(smu + so[j] * 4, gp[j]);
    CP_COMMIT();
    #pragma unroll
    for (int j = 0; j < 6; j++) cp16(smu + (STGW + so[j]) * 4, gp[j] + KC);
    CP_COMMIT();

    for (int c = 0; c < nch; c++) {
        int st = c % 3;
        cp_wait<1>();
        __syncthreads();

        uint32_t hA = smu + (uint32_t)(st * STGW) * 4;
        uint32_t hB = hA + 128 * RW * 4;

        #pragma unroll
        for (int ks = 0; ks < 4; ks++) {
            uint32_t ko = (uint32_t)(ks * 32);
            uint32_t a[2][4];
            #pragma unroll
            for (int i = 0; i < 2; i++)
                ldsm4(a[i], hA + (uint32_t)((wm * 32 + i * 16) * (RW * 4)) + ko + laneOff);
            uint32_t b[4][4];
            #pragma unroll
            for (int j2 = 0; j2 < 4; j2++)
                ldsm4(b[j2], hB + (uint32_t)((wn * 64 + j2 * 16) * (RW * 4)) + ko + laneOff);
            #pragma unroll
            for (int i = 0; i < 2; i++)
                #pragma unroll
                for (int j2 = 0; j2 < 4; j2++) {
                    mma16(acc[i][j2 * 2 + 0], a[i], b[j2][0], b[j2][2]);
                    mma16(acc[i][j2 * 2 + 1], a[i], b[j2][1], b[j2][3]);
                }
        }

        if (c + 2 < nch) {
            int st2 = (c + 2) % 3;
            int kb = (c + 2) * KC;
            #pragma unroll
            for (int j = 0; j < 6; j++)
                cp16(smu + (st2 * STGW + so[j]) * 4, gp[j] + kb);
        }
        CP_COMMIT();
    }

    #pragma unroll
    for (int i = 0; i < 2; i++) {
        int rbase = wm * 32 + i * 16 + gq;
        #pragma unroll
        for (int j = 0; j < 8; j++) {
            int col = dblk + wn * 64 + j * 8 + 2 * cq;
            #pragma unroll
            for (int half = 0; half < 2; half++) {
                int r = rbase + half * 8;
                if (r >= nvalid) continue;
                int tok = s_tok[r];
                float wt = s_wtv[r];
                float* dst = out + (size_t)tok * DIM + col;
                atomicAdd(dst + 0, acc[i][j][half * 2 + 0] * wt);
                atomicAdd(dst + 1, acc[i][j][half * 2 + 1] * wt);
            }
        }
    }
}

// ---------------- launch ----------------
extern "C" void kernel_launch(void* const* d_in, const int* in_sizes, int n_in,
                              void* d_out, int out_size) {
    const float* x   = (const float*)d_in[0];
    const float* gw  = (const float*)d_in[1];
    const float* w1  = (const float*)d_in[2];
    const float* w2  = (const float*)d_in[3];
    const float* w3  = (const float*)d_in[4];
    const float* sw1 = (const float*)d_in[5];
    const float* sw2 = (const float*)d_in[6];
    const float* sw3 = (const float*)d_in[7];
    float* out = (float*)d_out;

    void *p_w1, *p_w2, *p_w3, *p_sw1, *p_sw2, *p_sw3, *p_x;
    cudaGetSymbolAddress(&p_w1,  h_w1);
    cudaGetSymbolAddress(&p_w2,  h_w2);
    cudaGetSymbolAddress(&p_w3,  h_w3);
    cudaGetSymbolAddress(&p_sw1, h_sw1);
    cudaGetSymbolAddress(&p_sw2, h_sw2);
    cudaGetSymbolAddress(&p_sw3, h_sw3);
    cudaGetSymbolAddress(&p_x,   h_x);

    const int smBytes = 3 * STGW * 4;   // 165888
    cudaFuncSetAttribute((const void*)k_up,   cudaFuncAttributeMaxDynamicSharedMemorySize, smBytes);
    cudaFuncSetAttribute((const void*)k_down, cudaFuncAttributeMaxDynamicSharedMemorySize, smBytes);

    const int NW = NEXP * INTER * DIM / 4;
    const int NS = SHIN * DIM / 4;
    k_f2h<<<NW / 1024, 256>>>((const float4*)w1,  (uint2*)p_w1,  NW);
    k_f2h<<<NW / 1024, 256>>>((const float4*)w3,  (uint2*)p_w3,  NW);
    k_f2h<<<NS / 1024, 256>>>((const float4*)sw1, (uint2*)p_sw1, NS);
    k_f2h<<<NS / 1024, 256>>>((const float4*)sw3, (uint2*)p_sw3, NS);
    k_f2h<<<NS / 1024, 256>>>((const float4*)x,   (uint2*)p_x,   NS);

    k_zero<<<1, 32>>>();
    k_zero_out<<<(TT * DIM) / 1024, 256>>>(out);
    k_gate<<<TT, 128>>>(x, gw);
    k_build<<<1, 32>>>();
    k_scatter<<<NEXP, 256>>>();

    k_up<<<UP_RB + UP_SB, 512, smBytes>>>();

    // w2/sw2 conversions only needed by k_down; issue after k_up to shorten
    // the critical path ahead of the first GEMM.
    k_f2h<<<NW / 1024, 256>>>((const float4*)w2,  (uint2*)p_w2,  NW);
    k_f2h<<<NS / 1024, 256>>>((const float4*)sw2, (uint2*)p_sw2, NS);

    k_down<<<DN_RB + DN_SB, 512, smBytes>>>(out);
}

// round 17
// speedup vs baseline: 1.0309x; 1.0309x over previous
#include <cuda_runtime.h>
#include <cuda_fp16.h>
#include <math.h>
#include <stdint.h>

#define TT 2048
#define DIM 2048
#define NEXP 32
#define TOPK 4
#define INTER 1024
#define SHIN 2048
#define NA (TT*TOPK)
#define BM 128
#define MAXTILES (NA/BM + NEXP)   /* 96 */

#define KC 64                     /* K halfs per chunk */
#define RW 36                     /* words per fp16 stage row (32 data + 4 pad) */
#define STGW (384*RW)             /* 13824 words per stage (A 128 + B 256 rows) */

#define UP_RB   (MAXTILES * 8)    /* routed up: 96 x (1024/128) */
#define UP_SB   (16 * 16)         /* shared up: 16 x (2048/128) */
#define UP_TOT  (UP_RB + UP_SB)   /* 1024 */
#define UP_CW2  2048              /* w2 convert blocks fused into k_up */
#define UP_CSW2 128               /* sw2 convert blocks */
#define DN_RB   (MAXTILES * 8)
#define DN_SB   (16 * 8)

#define NW4 (NEXP*INTER*DIM/4)    /* 16777216 float4 per big weight */
#define NS4 (SHIN*DIM/4)          /* 1048576 float4 per small matrix */

// k_prep segment layout (256-thr blocks, 1024 float4 each)
#define PR_W1   0
#define PR_W3   (PR_W1 + NW4/1024)     /* 16384 */
#define PR_SW1  (PR_W3 + NW4/1024)     /* 32768 */
#define PR_SW3  (PR_SW1 + NS4/1024)    /* 33792 */
#define PR_X    (PR_SW3 + NS4/1024)    /* 34816 */
#define PR_ZO   (PR_X + NS4/1024)      /* 35840 */
#define PR_ZC   (PR_ZO + NS4/1024)     /* 36864 */
#define PR_TOT  (PR_ZC + 1)            /* 36865 */

// ---------------- device scratch ----------------
__device__ int   g_topi[TT*TOPK];
__device__ float g_topw[TT*TOPK];
__device__ int   g_cnt[NEXP];
__device__ int   g_off[NEXP+1];
__device__ int   g_tok[NA];
__device__ float g_wt[NA];
__device__ int   g_tile_e[MAXTILES];
__device__ int   g_tile_r0[MAXTILES];
__device__ int   g_tile_n[MAXTILES];
__device__ int   g_ntiles;

// fp16 copies (converted once per call)
__device__ __half h_w1[(size_t)NEXP*INTER*DIM];
__device__ __half h_w2[(size_t)NEXP*DIM*INTER];
__device__ __half h_w3[(size_t)NEXP*INTER*DIM];
__device__ __half h_sw1[(size_t)SHIN*DIM];
__device__ __half h_sw2[(size_t)DIM*SHIN];
__device__ __half h_sw3[(size_t)SHIN*DIM];
__device__ __half h_x[(size_t)TT*DIM];
__device__ __half h_h[(size_t)NA*INTER];
__device__ __half h_hs[(size_t)TT*SHIN];

// ---------------- helpers ----------------
__device__ __forceinline__ uint32_t smem_u32(const void* p) {
    uint32_t a;
    asm("{ .reg .u64 t; cvta.to.shared.u64 t, %1; cvt.u32.u64 %0, t; }" : "=r"(a) : "l"(p));
    return a;
}
__device__ __forceinline__ uint32_t pk16(float lo, float hi) {
    uint32_t r; asm("cvt.rn.f16x2.f32 %0, %1, %2;" : "=r"(r) : "f"(hi), "f"(lo)); return r;
}
__device__ __forceinline__ void cp16(uint32_t dst, const void* src) {
    asm volatile("cp.async.cg.shared.global [%0], [%1], 16;" :: "r"(dst), "l"(src));
}
#define CP_COMMIT() asm volatile("cp.async.commit_group;" ::: "memory")
template<int N>
__device__ __forceinline__ void cp_wait() {
    asm volatile("cp.async.wait_group %0;" :: "n"(N) : "memory");
}
__device__ __forceinline__ void mma16(float* c, const uint32_t* a, uint32_t b0, uint32_t b1) {
    asm volatile("mma.sync.aligned.m16n8k16.row.col.f32.f16.f16.f32 "
        "{%0,%1,%2,%3}, {%4,%5,%6,%7}, {%8,%9}, {%0,%1,%2,%3};"
        : "+f"(c[0]), "+f"(c[1]), "+f"(c[2]), "+f"(c[3])
        : "r"(a[0]), "r"(a[1]), "r"(a[2]), "r"(a[3]), "r"(b0), "r"(b1));
}
__device__ __forceinline__ void ldsm4(uint32_t* r, uint32_t addr) {
    asm volatile("ldmatrix.sync.aligned.m8n8.x4.shared.b16 {%0,%1,%2,%3}, [%4];"
        : "=r"(r[0]), "=r"(r[1]), "=r"(r[2]), "=r"(r[3]) : "r"(addr));
}
__device__ __forceinline__ float silu_f(float v) { return v / (1.0f + __expf(-v)); }

// convert a 4-float4 batch (ILP 4)
__device__ __forceinline__ void cv4(const float4* __restrict__ src,
                                    uint2* __restrict__ dst,
                                    int i0, int i1, int i2, int i3) {
    float4 v0 = __ldcs(src + i0);
    float4 v1 = __ldcs(src + i1);
    float4 v2 = __ldcs(src + i2);
    float4 v3 = __ldcs(src + i3);
    uint2 w0, w1, w2, w3;
    w0.x = pk16(v0.x, v0.y); w0.y = pk16(v0.z, v0.w);
    w1.x = pk16(v1.x, v1.y); w1.y = pk16(v1.z, v1.w);
    w2.x = pk16(v2.x, v2.y); w2.y = pk16(v2.z, v2.w);
    w3.x = pk16(v3.x, v3.y); w3.y = pk16(v3.z, v3.w);
    __stcs(dst + i0, w0);
    __stcs(dst + i1, w1);
    __stcs(dst + i2, w2);
    __stcs(dst + i3, w3);
}

// ---------------- k_prep: fused converts + zeroing (256 thr) --------------
__global__ __launch_bounds__(256) void k_prep(const float4* __restrict__ w1,
                                              const float4* __restrict__ w3,
                                              const float4* __restrict__ sw1,
                                              const float4* __restrict__ sw3,
                                              const float4* __restrict__ x,
                                              float4* __restrict__ out) {
    int bid = blockIdx.x, tid = threadIdx.x;
    if (bid < PR_ZO) {
        const float4* src; uint2* dst; int base;
        if (bid < PR_W3)       { src = w1;  dst = (uint2*)h_w1;  base = bid * 1024; }
        else if (bid < PR_SW1) { src = w3;  dst = (uint2*)h_w3;  base = (bid - PR_W3) * 1024; }
        else if (bid < PR_SW3) { src = sw1; dst = (uint2*)h_sw1; base = (bid - PR_SW1) * 1024; }
        else if (bid < PR_X)   { src = sw3; dst = (uint2*)h_sw3; base = (bid - PR_SW3) * 1024; }
        else                   { src = x;   dst = (uint2*)h_x;   base = (bid - PR_X) * 1024; }
        int b = base + tid;
        cv4(src, dst, b, b + 256, b + 512, b + 768);
    } else if (bid < PR_ZC) {
        int b = (bid - PR_ZO) * 1024 + tid;
        float4 z = make_float4(0.f, 0.f, 0.f, 0.f);
        out[b] = z; out[b + 256] = z; out[b + 512] = z; out[b + 768] = z;
    } else {
        if (tid < NEXP) g_cnt[tid] = 0;
    }
}

// ---------------- kernel 1: gate (fp32 exact) ----------------
__global__ __launch_bounds__(128) void k_gate(const float* __restrict__ x,
                                              const float* __restrict__ gw) {
    __shared__ float sx[DIM];
    __shared__ float slog[NEXP];
    int t = blockIdx.x;
    const float* xr = x + (size_t)t * DIM;
    for (int i = threadIdx.x * 4; i < DIM; i += 128 * 4)
        *(float4*)(sx + i) = *(const float4*)(xr + i);
    __syncthreads();

    int e = threadIdx.x >> 2, part = threadIdx.x & 3;
    const float* wr = gw + (size_t)e * DIM;
    float s = 0.f;
    for (int k = part * 4; k < DIM; k += 16) {
        float4 a = *(const float4*)(sx + k);
        float4 b = *(const float4*)(wr + k);
        s += a.x * b.x + a.y * b.y + a.z * b.z + a.w * b.w;
    }
    s += __shfl_down_sync(0xffffffffu, s, 2, 4);
    s += __shfl_down_sync(0xffffffffu, s, 1, 4);
    if (part == 0) slog[e] = s;
    __syncthreads();

    if (threadIdx.x < 32) {
        float sc = slog[threadIdx.x];
        float m = sc;
        for (int o = 16; o; o >>= 1) m = fmaxf(m, __shfl_xor_sync(0xffffffffu, m, o));
        float p = expf(sc - m);
        float sum = p;
        for (int o = 16; o; o >>= 1) sum += __shfl_xor_sync(0xffffffffu, sum, o);
        float v = p / sum;
        for (int r = 0; r < TOPK; r++) {
            float mv = v;
            for (int o = 16; o; o >>= 1) mv = fmaxf(mv, __shfl_xor_sync(0xffffffffu, mv, o));
            unsigned bal = __ballot_sync(0xffffffffu, v == mv);
            int idx = __ffs(bal) - 1;
            if (threadIdx.x == 0) {
                g_topi[t * TOPK + r] = idx;
                g_topw[t * TOPK + r] = mv;
                atomicAdd(&g_cnt[idx], 1);
            }
            if (threadIdx.x == idx) v = -1.f;
        }
    }
}

// ---------------- kernel 2: offsets + tile map (1 warp) ----------------
__global__ __launch_bounds__(32) void k_build() {
    int lane = threadIdx.x;
    int n = g_cnt[lane];
    int off = n;
    #pragma unroll
    for (int o = 1; o < 32; o <<= 1) {
        int v = __shfl_up_sync(0xffffffffu, off, o);
        if (lane >= o) off += v;
    }
    int excl = off - n;
    g_off[lane] = excl;
    if (lane == 31) g_off[NEXP] = off;

    int nt = (n + BM - 1) / BM;
    int tb = nt;
    #pragma unroll
    for (int o = 1; o < 32; o <<= 1) {
        int v = __shfl_up_sync(0xffffffffu, tb, o);
        if (lane >= o) tb += v;
    }
    int texcl = tb - nt;
    if (lane == 31) g_ntiles = tb;
    for (int t = 0; t < nt; t++) {
        g_tile_e[texcl + t]  = lane;
        g_tile_r0[texcl + t] = excl + t * BM;
        g_tile_n[texcl + t]  = min(BM, n - t * BM);
    }
}

// ---------------- kernel 3: parallel deterministic scatter ----------------
__global__ __launch_bounds__(256) void k_scatter() {
    int e = blockIdx.x, tid = threadIdx.x, w = tid >> 5, lane = tid & 31;
    __shared__ int wc[8];
    int t0 = w * 256;
    int cnt = 0;
    for (int i = 0; i < 8; i++) {
        int t = t0 + i * 32 + lane;
        bool f = false;
        #pragma unroll
        for (int k = 0; k < TOPK; k++) if (g_topi[t * TOPK + k] == e) f = true;
        cnt += __popc(__ballot_sync(0xffffffffu, f));
    }
    if (lane == 0) wc[w] = cnt;
    __syncthreads();
    int base = g_off[e];
    for (int ww = 0; ww < w; ww++) base += wc[ww];
    for (int i = 0; i < 8; i++) {
        int t = t0 + i * 32 + lane;
        float wt = 0.f; bool f = false;
        #pragma unroll
        for (int k = 0; k < TOPK; k++)
            if (g_topi[t * TOPK + k] == e) { f = true; wt = g_topw[t * TOPK + k]; }
        unsigned bal = __ballot_sync(0xffffffffu, f);
        int pos = base + __popc(bal & ((1u << lane) - 1u));
        if (f) { g_tok[pos] = t; g_wt[pos] = wt; }
        base += __popc(bal);
    }
}

// ---------------- merged up kernel + fused w2/sw2 convert ------------------
__global__ __launch_bounds__(512, 1) void k_up(const float4* __restrict__ w2f,
                                               const float4* __restrict__ sw2f) {
    constexpr int NCH = DIM / KC;             // 32

    extern __shared__ uint32_t sm[];
    __shared__ int s_tok[BM];

    int bid = blockIdx.x;
    int tid = threadIdx.x;

    // -------- fused convert blocks (run concurrently with GEMM tiles) ----
    if (bid >= UP_TOT) {
        int cb = bid - UP_TOT;
        const float4* src; uint2* dst; int base;
        if (cb < UP_CW2) { src = w2f;  dst = (uint2*)h_w2;  base = cb * 8192; }
        else             { src = sw2f; dst = (uint2*)h_sw2; base = (cb - UP_CW2) * 8192; }
        for (int jj = 0; jj < 4; jj++) {
            int b = base + jj * 2048 + tid;
            cv4(src, dst, b, b + 512, b + 1024, b + 1536);
        }
        return;
    }

    int e = 0, r0, nvalid = BM, jblk;
    const __half *pw1, *pw3;
    __half* dstH; int dstride, ni;
    bool routed = bid < UP_RB;
    if (routed) {
        int tile = bid >> 3;
        if (tile >= g_ntiles) return;
        jblk = (bid & 7) * 128;
        e = g_tile_e[tile]; r0 = g_tile_r0[tile]; nvalid = g_tile_n[tile];
        pw1 = h_w1; pw3 = h_w3; dstH = h_h; dstride = INTER; ni = INTER;
    } else {
        int sid = bid - UP_RB;
        int tile = sid >> 4;
        jblk = (sid & 15) * 128;
        r0 = tile * BM;
        pw1 = h_sw1; pw3 = h_sw3; dstH = h_hs; dstride = SHIN; ni = SHIN;
    }

    int wid = tid >> 5, lane = tid & 31;
    int wm = wid & 3, wn = wid >> 2;          // 4 x 4 warps
    int gq = lane >> 2, cq = lane & 3;

    if (tid < BM)
        s_tok[tid] = routed ? g_tok[r0 + min(tid, nvalid - 1)] : (r0 + tid);
    __syncthreads();

    const __half* gp[6];
    uint32_t so[6];
    uint32_t smu = smem_u32(sm);
    #pragma unroll
    for (int j = 0; j < 6; j++) {
        int id = tid + j * 512;
        int s = id & 7;
        if (id < 1024) {
            int r = id >> 3;
            so[j] = (uint32_t)(r * RW + s * 4);
            gp[j] = h_x + (size_t)s_tok[r] * DIM + s * 8;
        } else {
            int rb = (id - 1024) >> 3;
            so[j] = (uint32_t)((128 + rb) * RW + s * 4);
            if (rb < 128) gp[j] = pw1 + ((size_t)e * ni + jblk + rb) * DIM + s * 8;
            else          gp[j] = pw3 + ((size_t)e * ni + jblk + (rb - 128)) * DIM + s * 8;
        }
    }

    float acc1[2][4][4], acc3[2][4][4];
    #pragma unroll
    for (int i = 0; i < 2; i++)
        #pragma unroll
        for (int j = 0; j < 4; j++)
            #pragma unroll
            for (int q = 0; q < 4; q++) { acc1[i][j][q] = 0.f; acc3[i][j][q] = 0.f; }

    uint32_t laneOff = (uint32_t)((lane & 15) * (RW * 4) + ((lane & 16) ? 16 : 0));

    #pragma unroll
    for (int j = 0; j < 6; j++) cp16(smu + so[j] * 4, gp[j]);
    CP_COMMIT();
    #pragma unroll
    for (int j = 0; j < 6; j++) cp16(smu + (STGW + so[j]) * 4, gp[j] + KC);
    CP_COMMIT();

    for (int c = 0; c < NCH; c++) {
        int st = c % 3;
        cp_wait<1>();
        __syncthreads();

        uint32_t hA = smu + (uint32_t)(st * STGW) * 4;
        uint32_t hB = hA + 128 * RW * 4;

        #pragma unroll
        for (int ks = 0; ks < 4; ks++) {
            uint32_t ko = (uint32_t)(ks * 32);
            uint32_t a[2][4];
            #pragma unroll
            for (int i = 0; i < 2; i++)
                ldsm4(a[i], hA + (uint32_t)((wm * 32 + i * 16) * (RW * 4)) + ko + laneOff);
            uint32_t b1[2][4], b3[2][4];
            #pragma unroll
            for (int j2 = 0; j2 < 2; j2++) {
                int nb = wn * 32 + j2 * 16;
                ldsm4(b1[j2], hB + (uint32_t)(nb * (RW * 4)) + ko + laneOff);
                ldsm4(b3[j2], hB + (uint32_t)((128 + nb) * (RW * 4)) + ko + laneOff);
            }
            #pragma unroll
            for (int i = 0; i < 2; i++)
                #pragma unroll
                for (int j2 = 0; j2 < 2; j2++) {
                    mma16(acc1[i][j2 * 2 + 0], a[i], b1[j2][0], b1[j2][2]);
                    mma16(acc1[i][j2 * 2 + 1], a[i], b1[j2][1], b1[j2][3]);
                    mma16(acc3[i][j2 * 2 + 0], a[i], b3[j2][0], b3[j2][2]);
                    mma16(acc3[i][j2 * 2 + 1], a[i], b3[j2][1], b3[j2][3]);
                }
        }

        if (c + 2 < NCH) {
            int st2 = (c + 2) % 3;
            int kb = (c + 2) * KC;
            #pragma unroll
            for (int j = 0; j < 6; j++)
                cp16(smu + (st2 * STGW + so[j]) * 4, gp[j] + kb);
        }
        CP_COMMIT();
    }

    #pragma unroll
    for (int i = 0; i < 2; i++) {
        int rbase = wm * 32 + i * 16 + gq;
        #pragma unroll
        for (int j = 0; j < 4; j++) {
            int col = jblk + wn * 32 + j * 8 + 2 * cq;
            if (rbase < nvalid) {
                uint32_t o = pk16(silu_f(acc1[i][j][0]) * acc3[i][j][0],
                                  silu_f(acc1[i][j][1]) * acc3[i][j][1]);
                *(uint32_t*)(dstH + (size_t)(r0 + rbase) * dstride + col) = o;
            }
            if (rbase + 8 < nvalid) {
                uint32_t o = pk16(silu_f(acc1[i][j][2]) * acc3[i][j][2],
                                  silu_f(acc1[i][j][3]) * acc3[i][j][3]);
                *(uint32_t*)(dstH + (size_t)(r0 + rbase + 8) * dstride + col) = o;
            }
        }
    }
}

// ---------------- merged down kernel: 128x256, 512 thr, 3-stage -----------
__global__ __launch_bounds__(512, 1) void k_down(float* __restrict__ out) {
    extern __shared__ uint32_t sm[];
    __shared__ int   s_tok[BM];
    __shared__ float s_wtv[BM];

    int bid = blockIdx.x;
    int e = 0, r0, nvalid = BM, dblk, kd, nch;
    const __half* srcH; int sstride;
    const __half* pb;
    bool routed = bid < DN_RB;
    if (routed) {
        int tile = bid >> 3;
        if (tile >= g_ntiles) return;
        dblk = (bid & 7) * 256;
        e = g_tile_e[tile]; r0 = g_tile_r0[tile]; nvalid = g_tile_n[tile];
        srcH = h_h; sstride = INTER; kd = INTER; nch = INTER / KC;     // 16
        pb = h_w2;
    } else {
        int sid = bid - DN_RB;
        int tile = sid >> 3;
        dblk = (sid & 7) * 256;
        r0 = tile * BM;
        srcH = h_hs; sstride = SHIN; kd = SHIN; nch = SHIN / KC;       // 32
        pb = h_sw2;
    }

    int tid = threadIdx.x, wid = tid >> 5, lane = tid & 31;
    int wm = wid & 3, wn = wid >> 2;          // 4 x 4 warps
    int gq = lane >> 2, cq = lane & 3;

    if (tid < BM) {
        if (routed) {
            int ok = tid < nvalid;
            s_tok[tid] = ok ? g_tok[r0 + tid] : 0;
            s_wtv[tid] = ok ? g_wt[r0 + tid]  : 0.f;
        } else { s_tok[tid] = r0 + tid; s_wtv[tid] = 1.f; }
    }
    __syncthreads();

    const __half* gp[6];
    uint32_t so[6];
    uint32_t smu = smem_u32(sm);
    #pragma unroll
    for (int j = 0; j < 6; j++) {
        int id = tid + j * 512;
        int s = id & 7;
        if (id < 1024) {
            int r = id >> 3;
            so[j] = (uint32_t)(r * RW + s * 4);
            gp[j] = srcH + (size_t)min(r0 + r, (routed ? NA : TT) - 1) * sstride + s * 8;
        } else {
            int rb = (id - 1024) >> 3;
            so[j] = (uint32_t)((128 + rb) * RW + s * 4);
            gp[j] = pb + ((size_t)e * DIM + dblk + rb) * kd + s * 8;
        }
    }

    float acc[2][8][4];
    #pragma unroll
    for (int i = 0; i < 2; i++)
        #pragma unroll
        for (int j = 0; j < 8; j++)
            #pragma unroll
            for (int q = 0; q < 4; q++) acc[i][j][q] = 0.f;

    uint32_t laneOff = (uint32_t)((lane & 15) * (RW * 4) + ((lane & 16) ? 16 : 0));

    #pragma unroll
    for (int j = 0; j < 6; j++) cp16(smu + so[j] * 4, gp[j]);
    CP_COMMIT();
    #pragma unroll
    for (int j = 0; j < 6; j++) cp16(smu + (STGW + so[j]) * 4, gp[j] + KC);
    CP_COMMIT();

    for (int c = 0; c < nch; c++) {
        int st = c % 3;
        cp_wait<1>();
        __syncthreads();

        uint32_t hA = smu + (uint32_t)(st * STGW) * 4;
        uint32_t hB = hA + 128 * RW * 4;

        #pragma unroll
        for (int ks = 0; ks < 4; ks++) {
            uint32_t ko = (uint32_t)(ks * 32);
            uint32_t a[2][4];
            #pragma unroll
            for (int i = 0; i < 2; i++)
                ldsm4(a[i], hA + (uint32_t)((wm * 32 + i * 16) * (RW * 4)) + ko + laneOff);
            uint32_t b[4][4];
            #pragma unroll
            for (int j2 = 0; j2 < 4; j2++)
                ldsm4(b[j2], hB + (uint32_t)((wn * 64 + j2 * 16) * (RW * 4)) + ko + laneOff);
            #pragma unroll
            for (int i = 0; i < 2; i++)
                #pragma unroll
                for (int j2 = 0; j2 < 4; j2++) {
                    mma16(acc[i][j2 * 2 + 0], a[i], b[j2][0], b[j2][2]);
                    mma16(acc[i][j2 * 2 + 1], a[i], b[j2][1], b[j2][3]);
                }
        }

        if (c + 2 < nch) {
            int st2 = (c + 2) % 3;
            int kb = (c + 2) * KC;
            #pragma unroll
            for (int j = 0; j < 6; j++)
                cp16(smu + (st2 * STGW + so[j]) * 4, gp[j] + kb);
        }
        CP_COMMIT();
    }

    #pragma unroll
    for (int i = 0; i < 2; i++) {
        int rbase = wm * 32 + i * 16 + gq;
        #pragma unroll
        for (int j = 0; j < 8; j++) {
            int col = dblk + wn * 64 + j * 8 + 2 * cq;
            #pragma unroll
            for (int half = 0; half < 2; half++) {
                int r = rbase + half * 8;
                if (r >= nvalid) continue;
                int tok = s_tok[r];
                float wt = s_wtv[r];
                float* dst = out + (size_t)tok * DIM + col;
                atomicAdd(dst + 0, acc[i][j][half * 2 + 0] * wt);
                atomicAdd(dst + 1, acc[i][j][half * 2 + 1] * wt);
            }
        }
    }
}

// ---------------- launch ----------------
extern "C" void kernel_launch(void* const* d_in, const int* in_sizes, int n_in,
                              void* d_out, int out_size) {
    const float* x   = (const float*)d_in[0];
    const float* gw  = (const float*)d_in[1];
    const float* w1  = (const float*)d_in[2];
    const float* w2  = (const float*)d_in[3];
    const float* w3  = (const float*)d_in[4];
    const float* sw1 = (const float*)d_in[5];
    const float* sw2 = (const float*)d_in[6];
    const float* sw3 = (const float*)d_in[7];
    float* out = (float*)d_out;

    const int smBytes = 3 * STGW * 4;   // 165888
    cudaFuncSetAttribute((const void*)k_up,   cudaFuncAttributeMaxDynamicSharedMemorySize, smBytes);
    cudaFuncSetAttribute((const void*)k_down, cudaFuncAttributeMaxDynamicSharedMemorySize, smBytes);

    // fused converts (w1,w3,sw1,sw3,x) + zero out + zero counters
    k_prep<<<PR_TOT, 256>>>((const float4*)w1, (const float4*)w3,
                            (const float4*)sw1, (const float4*)sw3,
                            (const float4*)x, (float4*)out);

    k_gate<<<TT, 128>>>(x, gw);
    k_build<<<1, 32>>>();
    k_scatter<<<NEXP, 256>>>();

    // up GEMM + fused w2/sw2 conversion blocks
    k_up<<<UP_TOT + UP_CW2 + UP_CSW2, 512, smBytes>>>((const float4*)w2,
                                                      (const float4*)sw2);

    k_down<<<DN_RB + DN_SB, 512, smBytes>>>(out);
}